// round 14
// baseline (speedup 1.0000x reference)
#include <cuda_runtime.h>
#include <math.h>

#define S_LEN 2048
#define E_DIM 1024
#define NHEAD 8
#define DHEAD 128
#define EPS_F 1e-6f
#define QKSCALE 0.08838834764831845f  // 1/sqrt(128)

#define BM 128
#define BN 64

// scratch (per-head, per-position gate quantities)
__device__ float g_ipre[NHEAD * S_LEN];
__device__ float g_lf[NHEAD * S_LEN];
__device__ float g_cum[NHEAD * S_LEN];
__device__ float g_M[NHEAD * S_LEN];
__device__ float g_part[8][S_LEN][16];   // gate GEMM partials (1 MB)

// ---------------------------------------------------------------------------
// Kernel 1a: gate GEMM partials. (unchanged from R13 — verified correct)
// ---------------------------------------------------------------------------
__global__ __launch_bounds__(256, 1)
void gate_gemm_kernel(const float* __restrict__ q, const float* __restrict__ k,
                      const float* __restrict__ v,
                      const float* __restrict__ Wi, const float* __restrict__ Wf) {
    extern __shared__ float gsm[];
    float* Wsi = gsm;              // [3][128][8]
    float* Wsf = gsm + 3072;       // [3][128][8]
    float* Xs  = gsm + 6144;       // [128][129]

    int tid = threadIdx.x;
    int pB = blockIdx.x & 15;      // position chunk
    int cE = blockIdx.x >> 4;      // e chunk

    for (int idx = tid; idx < 3072; idx += 256) {
        int part = idx >> 10;
        int rem  = idx & 1023;
        int r = rem >> 3, col = rem & 7;
        int grow = part * 1024 + cE * 128 + r;
        Wsi[idx] = Wi[grow * 8 + col];
        Wsf[idx] = Wf[grow * 8 + col];
    }

    int half = tid & 1;
    int pl = tid >> 1;
    float acc[8] = {0,0,0,0,0,0,0,0};
    const float* Xsrc[3] = {q, k, v};

    #pragma unroll
    for (int part = 0; part < 3; part++) {
        __syncthreads();
        for (int l = tid; l < 4096; l += 256) {
            int r = l >> 5, c4 = (l & 31) << 2;
            float4 xv = *(const float4*)(Xsrc[part] + (size_t)(pB * 128 + r) * E_DIM + cE * 128 + c4);
            float* d = Xs + r * 129 + c4;
            d[0] = xv.x; d[1] = xv.y; d[2] = xv.z; d[3] = xv.w;
        }
        __syncthreads();
        const float* wp = (half ? Wsf : Wsi) + part * 1024;
        const float* xp = Xs + pl * 129;
        #pragma unroll 4
        for (int e = 0; e < 128; e++) {
            float xv = xp[e];
            float4 w0 = *(const float4*)(wp + e * 8);
            float4 w1 = *(const float4*)(wp + e * 8 + 4);
            acc[0] += xv * w0.x; acc[1] += xv * w0.y;
            acc[2] += xv * w0.z; acc[3] += xv * w0.w;
            acc[4] += xv * w1.x; acc[5] += xv * w1.y;
            acc[6] += xv * w1.z; acc[7] += xv * w1.w;
        }
    }
    float* outp = &g_part[cE][pB * 128 + pl][half * 8];
    *(float4*)outp       = make_float4(acc[0], acc[1], acc[2], acc[3]);
    *(float4*)(outp + 4) = make_float4(acc[4], acc[5], acc[6], acc[7]);
}

// ---------------------------------------------------------------------------
// Kernel 1b: reduce partials, add bias, logsigmoid. (unchanged)
// ---------------------------------------------------------------------------
__global__ void gate_reduce_kernel(const float* __restrict__ bi, const float* __restrict__ bf) {
    int idx = blockIdx.x * 256 + threadIdx.x;
    int p = idx >> 4, o = idx & 15;
    float s = 0.f;
    #pragma unroll
    for (int c = 0; c < 8; c++) s += g_part[c][p][o];
    if (o < 8) {
        g_ipre[o * S_LEN + p] = s + bi[o];
    } else {
        int h = o - 8;
        float fp = s + bf[h];
        g_lf[h * S_LEN + p] = fminf(fp, 0.f) - log1pf(expf(-fabsf(fp)));
    }
}

// ---------------------------------------------------------------------------
// Kernel 2: per-head scans, 1 block per head, 256 threads x 8 elems each.
// cum = cumsum(lf);  M = prefixmax(i_pre - cum)
// ---------------------------------------------------------------------------
__global__ __launch_bounds__(256, 1)
void scan_kernel() {
    __shared__ float wred[8];
    __shared__ float woff[8];
    int h = blockIdx.x;
    int tid = threadIdx.x;
    int lane = tid & 31, w = tid >> 5;
    int base = h * S_LEN + tid * 8;
    const float NEG_BIG = -1e30f;

    // ---- inclusive cumsum of lf ----
    float x[8];
    #pragma unroll
    for (int t = 0; t < 8; t++) x[t] = g_lf[base + t];
    #pragma unroll
    for (int t = 1; t < 8; t++) x[t] += x[t - 1];
    float tot = x[7];
    float ws = tot;
    #pragma unroll
    for (int o = 1; o < 32; o <<= 1) {
        float n = __shfl_up_sync(0xffffffffu, ws, o);
        if (lane >= o) ws += n;
    }
    if (lane == 31) wred[w] = ws;
    __syncthreads();
    if (tid == 0) {
        float a = 0.f;
        #pragma unroll
        for (int i = 0; i < 8; i++) { float t = wred[i]; woff[i] = a; a += t; }
    }
    __syncthreads();
    float off = woff[w] + (ws - tot);   // exclusive prefix for this thread
    float cum[8], c[8];
    #pragma unroll
    for (int t = 0; t < 8; t++) {
        cum[t] = off + x[t];
        g_cum[base + t] = cum[t];
        c[t] = g_ipre[base + t] - cum[t];
    }
    __syncthreads();

    // ---- inclusive prefix-max of c ----
    float m[8];
    m[0] = c[0];
    #pragma unroll
    for (int t = 1; t < 8; t++) m[t] = fmaxf(m[t - 1], c[t]);
    float mtot = m[7];
    float wm = mtot;
    #pragma unroll
    for (int o = 1; o < 32; o <<= 1) {
        float n = __shfl_up_sync(0xffffffffu, wm, o);
        if (lane >= o) wm = fmaxf(wm, n);
    }
    if (lane == 31) wred[w] = wm;
    __syncthreads();
    if (tid == 0) {
        float a = NEG_BIG;
        #pragma unroll
        for (int i = 0; i < 8; i++) { float t = wred[i]; woff[i] = a; a = fmaxf(a, t); }
    }
    __syncthreads();
    float em = wm;  // inclusive up to this thread within block-warp
    // exclusive-for-thread = max(block-exclusive-for-warp, warp-exclusive-for-thread)
    float wexcl = __shfl_up_sync(0xffffffffu, wm, 1);
    if (lane == 0) wexcl = NEG_BIG;
    em = fmaxf(woff[w], wexcl);
    #pragma unroll
    for (int t = 0; t < 8; t++) {
        em = fmaxf(em, c[t]);
        g_M[base + t] = em;
    }
}

// ---------------------------------------------------------------------------
// Kernel 3: fused causal mLSTM attention + normalizer + per-head LayerNorm
// BM=128 x BN=64 tiles, 512 threads, grid = 16 rowtiles x 8 heads = 128.
// Thread (ty2 0..31, tx 0..15): GEMM1 4x4 tile; GEMM2 4 rows x cols {4tx, 64+4tx}.
// ---------------------------------------------------------------------------
#define PS_STRIDE 68
#define SMEM_FLOATS (16384 + 8192 + 8192 + 128*PS_STRIDE + 128 + 128 + 64)

__device__ __forceinline__ int swzQ(int d, int i) {   // [128][128]
    return d * 128 + ((((i >> 2) ^ ((d >> 2) & 7)) << 2) | (i & 3));
}
__device__ __forceinline__ int swzK(int d, int i) {   // [128][64]
    return d * 64 + ((((i >> 2) ^ ((d >> 2) & 7)) << 2) | (i & 3));
}

__global__ __launch_bounds__(512, 1)
void mlstm_attn_kernel(const float* __restrict__ q, const float* __restrict__ k,
                       const float* __restrict__ v, const float* __restrict__ lnsc,
                       float* __restrict__ out) {
    extern __shared__ float sm[];
    float* QsT    = sm;                          // [128 d][128 m] swizzled
    float* KsT    = sm + 16384;                  // [128 d][64 n] swizzled
    float* Vs     = sm + 24576;                  // [64 n][128 d] row-major
    float* Ps     = sm + 32768;                  // [128][PS_STRIDE]
    float* rowCum = sm + 32768 + 128 * PS_STRIDE;
    float* rowM   = rowCum + 128;
    float* ecol   = rowM + 128;

    int tid = threadIdx.x;
    int ty2 = tid >> 4;     // 0..31 (4-row group)
    int tx  = tid & 15;     // 0..15
    int head = blockIdx.x & 7;
    int rt   = blockIdx.x >> 3;    // 0..15
    int i0 = rt * BM;

    // load Q tile [BM][128] -> transposed + swizzled  (8 float4 per thread)
    #pragma unroll
    for (int it = 0; it < 8; it++) {
        int lin = tid + it * 512;       // 0..4095
        int r  = lin >> 5;              // 0..127
        int c4 = (lin & 31) << 2;       // 0..124
        float4 val = *(const float4*)(q + (size_t)(i0 + r) * E_DIM + head * DHEAD + c4);
        QsT[swzQ(c4 + 0, r)] = val.x;
        QsT[swzQ(c4 + 1, r)] = val.y;
        QsT[swzQ(c4 + 2, r)] = val.z;
        QsT[swzQ(c4 + 3, r)] = val.w;
    }
    if (tid < 128) {
        rowCum[tid] = g_cum[head * S_LEN + i0 + tid];
        rowM[tid]   = g_M[head * S_LEN + i0 + tid];
    }
    __syncthreads();
    float Mt = rowM[127];   // prefix-max nondecreasing -> tile max

    float o[4][8];          // [row ii][col: j<4 -> 4tx+j, j>=4 -> 64+4tx+(j-4)]
    float den[4] = {0.f, 0.f, 0.f, 0.f};
    #pragma unroll
    for (int ii = 0; ii < 4; ii++)
        #pragma unroll
        for (int jj = 0; jj < 8; jj++) o[ii][jj] = 0.f;

    int ntiles = 2 * rt + 2;
    for (int jt = 0; jt < ntiles; jt++) {
        int j0 = jt * BN;
        // load K tile [BN][128] -> KsT transposed/swizzled; V row-major (4 f4 each)
        #pragma unroll
        for (int it = 0; it < 4; it++) {
            int lin = tid + it * 512;   // 0..2047
            int r  = lin >> 5;          // 0..63
            int c4 = (lin & 31) << 2;
            float4 kv = *(const float4*)(k + (size_t)(j0 + r) * E_DIM + head * DHEAD + c4);
            KsT[swzK(c4 + 0, r)] = kv.x;
            KsT[swzK(c4 + 1, r)] = kv.y;
            KsT[swzK(c4 + 2, r)] = kv.z;
            KsT[swzK(c4 + 3, r)] = kv.w;
            float4 vv = *(const float4*)(v + (size_t)(j0 + r) * E_DIM + head * DHEAD + c4);
            *(float4*)(Vs + r * 128 + c4) = vv;
        }
        if (tid < 64) {
            int j = head * S_LEN + j0 + tid;
            float c = g_ipre[j] - g_cum[j];
            ecol[tid] = expf(c - Mt) * QKSCALE;
        }
        __syncthreads();

        // GEMM1: S[128x64] = Q Kt over d=128, 4x4 per thread
        float sacc[4][4];
        #pragma unroll
        for (int ii = 0; ii < 4; ii++)
            #pragma unroll
            for (int jj = 0; jj < 4; jj++) sacc[ii][jj] = 0.f;

        #pragma unroll 4
        for (int kk = 0; kk < 128; kk++) {
            int sw = (kk >> 2) & 7;
            float4 a = *(const float4*)(QsT + kk * 128 + ((ty2 ^ sw) << 2));
            float4 b = *(const float4*)(KsT + kk * 64 + ((tx ^ sw) << 2));
            float av[4] = {a.x, a.y, a.z, a.w};
            float bv[4] = {b.x, b.y, b.z, b.w};
            #pragma unroll
            for (int ii = 0; ii < 4; ii++)
                #pragma unroll
                for (int jj = 0; jj < 4; jj++)
                    sacc[ii][jj] += av[ii] * bv[jj];
        }

        // decay + causal mask (only last two col tiles can touch diagonal), write P'
        bool needmask = (j0 >= i0);
        #pragma unroll
        for (int ii = 0; ii < 4; ii++) {
            int ig = i0 + 4 * ty2 + ii;
            #pragma unroll
            for (int jj = 0; jj < 4; jj++) {
                int jl = 4 * tx + jj;
                float p = sacc[ii][jj] * ecol[jl];
                if (needmask && (j0 + jl > ig)) p = 0.f;
                Ps[(4 * ty2 + ii) * PS_STRIDE + jl] = p;
            }
        }
        __syncthreads();

        // GEMM2: O += P' V  (float4 P reads, conflict-free float4 V reads)
        #pragma unroll 1
        for (int kb = 0; kb < 64; kb += 4) {
            float pr[4][4];
            #pragma unroll
            for (int ii = 0; ii < 4; ii++)
                *(float4*)pr[ii] = *(const float4*)(Ps + (4 * ty2 + ii) * PS_STRIDE + kb);
            #pragma unroll
            for (int u = 0; u < 4; u++) {
                const float* vrow = Vs + (kb + u) * 128;
                float4 va = *(const float4*)(vrow + 4 * tx);
                float4 vb = *(const float4*)(vrow + 64 + 4 * tx);
                #pragma unroll
                for (int ii = 0; ii < 4; ii++) {
                    float p = pr[ii][u];
                    o[ii][0] += p * va.x;
                    o[ii][1] += p * va.y;
                    o[ii][2] += p * va.z;
                    o[ii][3] += p * va.w;
                    o[ii][4] += p * vb.x;
                    o[ii][5] += p * vb.y;
                    o[ii][6] += p * vb.z;
                    o[ii][7] += p * vb.w;
                    den[ii] += p;
                }
            }
        }
        __syncthreads();  // before next tile overwrites K/V/ecol
    }

    // epilogue: normalizer + per-head LayerNorm, float4 stores
    float4 ls0 = *(const float4*)(lnsc + head * DHEAD + 4 * tx);
    float4 ls1 = *(const float4*)(lnsc + head * DHEAD + 64 + 4 * tx);
    #pragma unroll
    for (int ii = 0; ii < 4; ii++) {
        int r = 4 * ty2 + ii;
        float er = expf(Mt - rowM[r]);
        float lower = expf(-(rowCum[r] + rowM[r]));   // exp(-max_log_D)
        float dt = den[ii] * er;
        float norm = fmaxf(fabsf(dt), lower) + EPS_F;
        float inv = er / norm;
        float hv[8];
        float ssum = 0.f, ssq = 0.f;
        #pragma unroll
        for (int qq = 0; qq < 8; qq++) {
            hv[qq] = o[ii][qq] * inv;
            ssum += hv[qq];
            ssq  += hv[qq] * hv[qq];
        }
        #pragma unroll
        for (int ofs = 1; ofs < 16; ofs <<= 1) {
            ssum += __shfl_xor_sync(0xffffffffu, ssum, ofs);
            ssq  += __shfl_xor_sync(0xffffffffu, ssq,  ofs);
        }
        float mean = ssum * (1.f / 128.f);
        float var  = ssq * (1.f / 128.f) - mean * mean;
        float rstd = rsqrtf(var + EPS_F);
        float* op = out + (size_t)(i0 + r) * E_DIM + head * DHEAD;
        float4 r0, r1;
        r0.x = (hv[0] - mean) * rstd * ls0.x;
        r0.y = (hv[1] - mean) * rstd * ls0.y;
        r0.z = (hv[2] - mean) * rstd * ls0.z;
        r0.w = (hv[3] - mean) * rstd * ls0.w;
        r1.x = (hv[4] - mean) * rstd * ls1.x;
        r1.y = (hv[5] - mean) * rstd * ls1.y;
        r1.z = (hv[6] - mean) * rstd * ls1.z;
        r1.w = (hv[7] - mean) * rstd * ls1.w;
        *(float4*)(op + 4 * tx)      = r0;
        *(float4*)(op + 64 + 4 * tx) = r1;
    }
}

// ---------------------------------------------------------------------------
extern "C" void kernel_launch(void* const* d_in, const int* in_sizes, int n_in,
                              void* d_out, int out_size) {
    const float* q   = (const float*)d_in[0];
    const float* k   = (const float*)d_in[1];
    const float* v   = (const float*)d_in[2];
    const float* Wi  = (const float*)d_in[3];
    const float* bi  = (const float*)d_in[4];
    const float* Wf  = (const float*)d_in[5];
    const float* bf  = (const float*)d_in[6];
    const float* lns = (const float*)d_in[7];
    float* out = (float*)d_out;

    size_t gate_smem = (size_t)(3072 + 3072 + 128 * 129) * sizeof(float);
    cudaFuncSetAttribute(gate_gemm_kernel,
                         cudaFuncAttributeMaxDynamicSharedMemorySize, (int)gate_smem);
    gate_gemm_kernel<<<128, 256, gate_smem>>>(q, k, v, Wi, Wf);
    gate_reduce_kernel<<<128, 256>>>(bi, bf);
    scan_kernel<<<NHEAD, 256>>>();

    size_t smem_bytes = (size_t)SMEM_FLOATS * sizeof(float);
    cudaFuncSetAttribute(mlstm_attn_kernel,
                         cudaFuncAttributeMaxDynamicSharedMemorySize, (int)smem_bytes);
    mlstm_attn_kernel<<<128, 512, smem_bytes>>>(q, k, v, lns, out);
}

// round 15
// speedup vs baseline: 1.7080x; 1.7080x over previous
#include <cuda_runtime.h>
#include <math.h>

#define S_LEN 2048
#define E_DIM 1024
#define NHEAD 8
#define DHEAD 128
#define EPS_F 1e-6f
#define QKSCALE 0.08838834764831845f  // 1/sqrt(128)

#define BM 64
#define BN 64

// scratch (per-head, per-position gate quantities)
__device__ float g_ipre[NHEAD * S_LEN];
__device__ float g_lf[NHEAD * S_LEN];
__device__ float g_cum[NHEAD * S_LEN];
__device__ float g_M[NHEAD * S_LEN];
__device__ float g_part[8][S_LEN][16];   // gate GEMM partials (1 MB)

// ---------------------------------------------------------------------------
// Kernel 1a: gate GEMM partials. (verified correct, ~10us)
// ---------------------------------------------------------------------------
__global__ __launch_bounds__(256, 1)
void gate_gemm_kernel(const float* __restrict__ q, const float* __restrict__ k,
                      const float* __restrict__ v,
                      const float* __restrict__ Wi, const float* __restrict__ Wf) {
    extern __shared__ float gsm[];
    float* Wsi = gsm;              // [3][128][8]
    float* Wsf = gsm + 3072;       // [3][128][8]
    float* Xs  = gsm + 6144;       // [128][129]

    int tid = threadIdx.x;
    int pB = blockIdx.x & 15;      // position chunk
    int cE = blockIdx.x >> 4;      // e chunk

    for (int idx = tid; idx < 3072; idx += 256) {
        int part = idx >> 10;
        int rem  = idx & 1023;
        int r = rem >> 3, col = rem & 7;
        int grow = part * 1024 + cE * 128 + r;
        Wsi[idx] = Wi[grow * 8 + col];
        Wsf[idx] = Wf[grow * 8 + col];
    }

    int half = tid & 1;
    int pl = tid >> 1;
    float acc[8] = {0,0,0,0,0,0,0,0};
    const float* Xsrc[3] = {q, k, v};

    #pragma unroll
    for (int part = 0; part < 3; part++) {
        __syncthreads();
        for (int l = tid; l < 4096; l += 256) {
            int r = l >> 5, c4 = (l & 31) << 2;
            float4 xv = *(const float4*)(Xsrc[part] + (size_t)(pB * 128 + r) * E_DIM + cE * 128 + c4);
            float* d = Xs + r * 129 + c4;
            d[0] = xv.x; d[1] = xv.y; d[2] = xv.z; d[3] = xv.w;
        }
        __syncthreads();
        const float* wp = (half ? Wsf : Wsi) + part * 1024;
        const float* xp = Xs + pl * 129;
        #pragma unroll 4
        for (int e = 0; e < 128; e++) {
            float xv = xp[e];
            float4 w0 = *(const float4*)(wp + e * 8);
            float4 w1 = *(const float4*)(wp + e * 8 + 4);
            acc[0] += xv * w0.x; acc[1] += xv * w0.y;
            acc[2] += xv * w0.z; acc[3] += xv * w0.w;
            acc[4] += xv * w1.x; acc[5] += xv * w1.y;
            acc[6] += xv * w1.z; acc[7] += xv * w1.w;
        }
    }
    float* outp = &g_part[cE][pB * 128 + pl][half * 8];
    *(float4*)outp       = make_float4(acc[0], acc[1], acc[2], acc[3]);
    *(float4*)(outp + 4) = make_float4(acc[4], acc[5], acc[6], acc[7]);
}

// ---------------------------------------------------------------------------
// Kernel 1b: reduce partials, add bias, logsigmoid. (unchanged)
// ---------------------------------------------------------------------------
__global__ void gate_reduce_kernel(const float* __restrict__ bi, const float* __restrict__ bf) {
    int idx = blockIdx.x * 256 + threadIdx.x;
    int p = idx >> 4, o = idx & 15;
    float s = 0.f;
    #pragma unroll
    for (int c = 0; c < 8; c++) s += g_part[c][p][o];
    if (o < 8) {
        g_ipre[o * S_LEN + p] = s + bi[o];
    } else {
        int h = o - 8;
        float fp = s + bf[h];
        g_lf[h * S_LEN + p] = fminf(fp, 0.f) - log1pf(expf(-fabsf(fp)));
    }
}

// ---------------------------------------------------------------------------
// Kernel 2: per-head scans, 1 block per head (R14 version — verified, ~3us)
// ---------------------------------------------------------------------------
__global__ __launch_bounds__(256, 1)
void scan_kernel() {
    __shared__ float wred[8];
    __shared__ float woff[8];
    int h = blockIdx.x;
    int tid = threadIdx.x;
    int lane = tid & 31, w = tid >> 5;
    int base = h * S_LEN + tid * 8;
    const float NEG_BIG = -1e30f;

    // ---- inclusive cumsum of lf ----
    float x[8];
    #pragma unroll
    for (int t = 0; t < 8; t++) x[t] = g_lf[base + t];
    #pragma unroll
    for (int t = 1; t < 8; t++) x[t] += x[t - 1];
    float tot = x[7];
    float ws = tot;
    #pragma unroll
    for (int o = 1; o < 32; o <<= 1) {
        float n = __shfl_up_sync(0xffffffffu, ws, o);
        if (lane >= o) ws += n;
    }
    if (lane == 31) wred[w] = ws;
    __syncthreads();
    if (tid == 0) {
        float a = 0.f;
        #pragma unroll
        for (int i = 0; i < 8; i++) { float t = wred[i]; woff[i] = a; a += t; }
    }
    __syncthreads();
    float off = woff[w] + (ws - tot);   // exclusive prefix for this thread
    float cum[8], c[8];
    #pragma unroll
    for (int t = 0; t < 8; t++) {
        cum[t] = off + x[t];
        g_cum[base + t] = cum[t];
        c[t] = g_ipre[base + t] - cum[t];
    }
    __syncthreads();

    // ---- inclusive prefix-max of c ----
    float m[8];
    m[0] = c[0];
    #pragma unroll
    for (int t = 1; t < 8; t++) m[t] = fmaxf(m[t - 1], c[t]);
    float mtot = m[7];
    float wm = mtot;
    #pragma unroll
    for (int o = 1; o < 32; o <<= 1) {
        float n = __shfl_up_sync(0xffffffffu, wm, o);
        if (lane >= o) wm = fmaxf(wm, n);
    }
    if (lane == 31) wred[w] = wm;
    __syncthreads();
    if (tid == 0) {
        float a = NEG_BIG;
        #pragma unroll
        for (int i = 0; i < 8; i++) { float t = wred[i]; woff[i] = a; a = fmaxf(a, t); }
    }
    __syncthreads();
    float wexcl = __shfl_up_sync(0xffffffffu, wm, 1);
    if (lane == 0) wexcl = NEG_BIG;
    float em = fmaxf(woff[w], wexcl);
    #pragma unroll
    for (int t = 0; t < 8; t++) {
        em = fmaxf(em, c[t]);
        g_M[base + t] = em;
    }
}

// ---------------------------------------------------------------------------
// Kernel 3: fused causal mLSTM attention (R13 frame: 256 thr, BM=64 pairing)
// + vectorized GEMM2 (cols {4tx, 64+4tx}), den in P-stage, f4 P/V/out.
// grid = 128 blocks (16 balanced row-tile pairs x 8 heads), 256 threads.
// ---------------------------------------------------------------------------
#define PS_STRIDE 68
#define SMEM_FLOATS (8192 + 8192 + 8192 + 64*PS_STRIDE + 64 + 64 + 64)

__device__ __forceinline__ int swz_idx(int d, int i) {
    // [128][64] transposed layout, XOR swizzle on 4-float chunks
    return d * 64 + ((((i >> 2) ^ ((d >> 2) & 7)) << 2) | (i & 3));
}

__global__ __launch_bounds__(256, 1)
void mlstm_attn_kernel(const float* __restrict__ q, const float* __restrict__ k,
                       const float* __restrict__ v, const float* __restrict__ lnsc,
                       float* __restrict__ out) {
    extern __shared__ float sm[];
    float* QsT    = sm;                        // [128][64] swizzled
    float* KsT    = sm + 8192;                 // [128][64] swizzled
    float* Vs     = sm + 16384;                // [64][128] row-major
    float* Ps     = sm + 24576;                // [64][PS_STRIDE]
    float* rowCum = sm + 24576 + 64 * PS_STRIDE;
    float* rowM   = rowCum + 64;
    float* ecol   = rowM + 64;

    int tid = threadIdx.x;
    int ty = tid >> 4;      // 0..15 (row group)
    int tx = tid & 15;      // 0..15 (col group)
    int head = blockIdx.x & 7;
    int pairIdx = blockIdx.x >> 3;   // 0..15

    for (int part = 0; part < 2; part++) {
        int rt = (part == 0) ? (31 - pairIdx) : pairIdx;  // big row-tiles first
        int i0 = rt * BM;

        // load Q tile -> transposed + swizzled
        #pragma unroll
        for (int it = 0; it < 8; it++) {
            int lin = tid + it * 256;       // 0..2047
            int r  = lin >> 5;              // 0..63
            int c4 = (lin & 31) << 2;       // 0..124
            float4 val = *(const float4*)(q + (size_t)(i0 + r) * E_DIM + head * DHEAD + c4);
            QsT[swz_idx(c4 + 0, r)] = val.x;
            QsT[swz_idx(c4 + 1, r)] = val.y;
            QsT[swz_idx(c4 + 2, r)] = val.z;
            QsT[swz_idx(c4 + 3, r)] = val.w;
        }
        if (tid < 64) {
            rowCum[tid] = g_cum[head * S_LEN + i0 + tid];
            rowM[tid]   = g_M[head * S_LEN + i0 + tid];
        }
        __syncthreads();
        float Mt = rowM[63];   // prefix-max is nondecreasing -> tile max

        float o[4][8];      // [row ii][col: j<4 -> 4tx+j ; j>=4 -> 64+4tx+(j-4)]
        float den[4] = {0.f, 0.f, 0.f, 0.f};
        #pragma unroll
        for (int ii = 0; ii < 4; ii++)
            #pragma unroll
            for (int qq = 0; qq < 8; qq++) o[ii][qq] = 0.f;

        int ntiles = i0 / BN + 1;
        for (int jt = 0; jt < ntiles; jt++) {
            int j0 = jt * BN;
            // load K (transposed+swizzled) and V (row-major)
            #pragma unroll
            for (int it = 0; it < 8; it++) {
                int lin = tid + it * 256;
                int r  = lin >> 5;
                int c4 = (lin & 31) << 2;
                float4 kv = *(const float4*)(k + (size_t)(j0 + r) * E_DIM + head * DHEAD + c4);
                KsT[swz_idx(c4 + 0, r)] = kv.x;
                KsT[swz_idx(c4 + 1, r)] = kv.y;
                KsT[swz_idx(c4 + 2, r)] = kv.z;
                KsT[swz_idx(c4 + 3, r)] = kv.w;
                float4 vv = *(const float4*)(v + (size_t)(j0 + r) * E_DIM + head * DHEAD + c4);
                *(float4*)(Vs + r * 128 + c4) = vv;
            }
            if (tid < 64) {
                int j = head * S_LEN + j0 + tid;
                float c = g_ipre[j] - g_cum[j];
                ecol[tid] = expf(c - Mt) * QKSCALE;
            }
            __syncthreads();

            // GEMM1: S[64x64] = Q Kt over d=128, 4x4 per thread
            float sacc[4][4];
            #pragma unroll
            for (int ii = 0; ii < 4; ii++)
                #pragma unroll
                for (int jj = 0; jj < 4; jj++) sacc[ii][jj] = 0.f;

            #pragma unroll 8
            for (int kk = 0; kk < 128; kk++) {
                int sw = (kk >> 2) & 7;
                float4 a = *(const float4*)(QsT + kk * 64 + ((ty ^ sw) << 2));
                float4 b = *(const float4*)(KsT + kk * 64 + ((tx ^ sw) << 2));
                float av[4] = {a.x, a.y, a.z, a.w};
                float bv[4] = {b.x, b.y, b.z, b.w};
                #pragma unroll
                for (int ii = 0; ii < 4; ii++)
                    #pragma unroll
                    for (int jj = 0; jj < 4; jj++)
                        sacc[ii][jj] += av[ii] * bv[jj];
            }

            // P stage: decay multiply + causal mask on diag tile,
            // den accumulated here (thread-local over own 4 cols), f4 P writes.
            bool diag = (j0 == i0);
            float4 ec = *(const float4*)(ecol + 4 * tx);
            #pragma unroll
            for (int ii = 0; ii < 4; ii++) {
                int ig = i0 + 4 * ty + ii;
                float p0 = sacc[ii][0] * ec.x;
                float p1 = sacc[ii][1] * ec.y;
                float p2 = sacc[ii][2] * ec.z;
                float p3 = sacc[ii][3] * ec.w;
                if (diag) {
                    int jg = j0 + 4 * tx;
                    if (jg + 0 > ig) p0 = 0.f;
                    if (jg + 1 > ig) p1 = 0.f;
                    if (jg + 2 > ig) p2 = 0.f;
                    if (jg + 3 > ig) p3 = 0.f;
                }
                den[ii] += (p0 + p1) + (p2 + p3);
                *(float4*)(Ps + (4 * ty + ii) * PS_STRIDE + 4 * tx) =
                    make_float4(p0, p1, p2, p3);
            }
            __syncthreads();

            // GEMM2: O += P' V  (f4 P reads per 4 kk, 2x f4 V reads per kk)
            #pragma unroll 1
            for (int kb = 0; kb < 64; kb += 4) {
                float pr[4][4];
                #pragma unroll
                for (int ii = 0; ii < 4; ii++)
                    *(float4*)pr[ii] = *(const float4*)(Ps + (4 * ty + ii) * PS_STRIDE + kb);
                #pragma unroll
                for (int u = 0; u < 4; u++) {
                    const float* vrow = Vs + (kb + u) * 128;
                    float4 va = *(const float4*)(vrow + 4 * tx);
                    float4 vb = *(const float4*)(vrow + 64 + 4 * tx);
                    #pragma unroll
                    for (int ii = 0; ii < 4; ii++) {
                        float p = pr[ii][u];
                        o[ii][0] += p * va.x;
                        o[ii][1] += p * va.y;
                        o[ii][2] += p * va.z;
                        o[ii][3] += p * va.w;
                        o[ii][4] += p * vb.x;
                        o[ii][5] += p * vb.y;
                        o[ii][6] += p * vb.z;
                        o[ii][7] += p * vb.w;
                    }
                }
            }
            __syncthreads();  // before next tile overwrites K/V/ecol
        }

        // den: reduce across the 16 tx threads of each row group (lanes xor<16)
        #pragma unroll
        for (int ii = 0; ii < 4; ii++) {
            #pragma unroll
            for (int ofs = 1; ofs < 16; ofs <<= 1)
                den[ii] += __shfl_xor_sync(0xffffffffu, den[ii], ofs);
        }

        // epilogue: normalizer + per-head LayerNorm, f4 stores
        float4 ls0 = *(const float4*)(lnsc + head * DHEAD + 4 * tx);
        float4 ls1 = *(const float4*)(lnsc + head * DHEAD + 64 + 4 * tx);
        #pragma unroll
        for (int ii = 0; ii < 4; ii++) {
            int r = 4 * ty + ii;
            float er = expf(Mt - rowM[r]);
            float lower = expf(-(rowCum[r] + rowM[r]));   // exp(-max_log_D)
            float dt = den[ii] * er;
            float norm = fmaxf(fabsf(dt), lower) + EPS_F;
            float inv = er / norm;
            float hv[8];
            float ssum = 0.f, ssq = 0.f;
            #pragma unroll
            for (int qq = 0; qq < 8; qq++) {
                hv[qq] = o[ii][qq] * inv;
                ssum += hv[qq];
                ssq  += hv[qq] * hv[qq];
            }
            #pragma unroll
            for (int ofs = 1; ofs < 16; ofs <<= 1) {
                ssum += __shfl_xor_sync(0xffffffffu, ssum, ofs);
                ssq  += __shfl_xor_sync(0xffffffffu, ssq,  ofs);
            }
            float mean = ssum * (1.f / 128.f);
            float var  = ssq * (1.f / 128.f) - mean * mean;
            float rstd = rsqrtf(var + EPS_F);
            float* op = out + (size_t)(i0 + r) * E_DIM + head * DHEAD;
            float4 r0, r1;
            r0.x = (hv[0] - mean) * rstd * ls0.x;
            r0.y = (hv[1] - mean) * rstd * ls0.y;
            r0.z = (hv[2] - mean) * rstd * ls0.z;
            r0.w = (hv[3] - mean) * rstd * ls0.w;
            r1.x = (hv[4] - mean) * rstd * ls1.x;
            r1.y = (hv[5] - mean) * rstd * ls1.y;
            r1.z = (hv[6] - mean) * rstd * ls1.z;
            r1.w = (hv[7] - mean) * rstd * ls1.w;
            *(float4*)(op + 4 * tx)      = r0;
            *(float4*)(op + 64 + 4 * tx) = r1;
        }
        __syncthreads();  // before next part reuses smem
    }
}

// ---------------------------------------------------------------------------
extern "C" void kernel_launch(void* const* d_in, const int* in_sizes, int n_in,
                              void* d_out, int out_size) {
    const float* q   = (const float*)d_in[0];
    const float* k   = (const float*)d_in[1];
    const float* v   = (const float*)d_in[2];
    const float* Wi  = (const float*)d_in[3];
    const float* bi  = (const float*)d_in[4];
    const float* Wf  = (const float*)d_in[5];
    const float* bf  = (const float*)d_in[6];
    const float* lns = (const float*)d_in[7];
    float* out = (float*)d_out;

    size_t gate_smem = (size_t)(3072 + 3072 + 128 * 129) * sizeof(float);
    cudaFuncSetAttribute(gate_gemm_kernel,
                         cudaFuncAttributeMaxDynamicSharedMemorySize, (int)gate_smem);
    gate_gemm_kernel<<<128, 256, gate_smem>>>(q, k, v, Wi, Wf);
    gate_reduce_kernel<<<128, 256>>>(bi, bf);
    scan_kernel<<<NHEAD, 256>>>();

    size_t smem_bytes = (size_t)SMEM_FLOATS * sizeof(float);
    cudaFuncSetAttribute(mlstm_attn_kernel,
                         cudaFuncAttributeMaxDynamicSharedMemorySize, (int)smem_bytes);
    mlstm_attn_kernel<<<128, 256, smem_bytes>>>(q, k, v, lns, out);
}